// round 15
// baseline (speedup 1.0000x reference)
#include <cuda_runtime.h>
#include <cuda_fp16.h>
#include <cstdint>
#include <math.h>

// ---------------------------------------------------------------------------
// RelNet forward.
// conv stack: SMEM-resident conv3x3 s2 (+bias+relu), BN(prev) folded into
// load, BN stats(this) fused in epilogue. Row-splits: L1 x4, L2 x2, L3 x2.
// g-stack: ONE fused kernel per 128 pair-rows, 512 threads / 16 warps,
//   stages split into 4 N-quarter passes with cp.async DOUBLE-BUFFERED
//   weight quarters (64x256 fp16) -> weight loads fully overlapped with
//   compute; first quarter overlaps the P/Q/R tile build.
//   fp16 HMMA (mma.sync m16n8k16, fp32 accum), pairsum -> fp32 atomics.
// objproj: one block per image, g1w rows cached in registers (25x reuse).
// f1,fc2 fp32 SGEMM -> fc3 + log_softmax.
// tcgen05 unavailable: harness PTX targets baseline sm_103 which rejects it.
// ---------------------------------------------------------------------------

#define BATCH 512
#define FS 24
#define OBJ 25
#define HID 256
#define NPAIR (BATCH * OBJ * OBJ)   // 320000

// ------------------------- scratch (static device) -------------------------
__device__ float g_c1[BATCH * FS * 40 * 40];
__device__ float g_c2[BATCH * FS * 20 * 20];
__device__ float g_c3[BATCH * FS * 10 * 10];
__device__ float g_c4[BATCH * FS * 5 * 5];
__device__ float g_stats4[4][48];             // per-layer BN stats (sum, sumsq)
__device__ float g_P[BATCH * OBJ * HID];
__device__ float g_Q[BATCH * OBJ * HID];
__device__ float g_R[BATCH * HID];
__device__ __half g_wh[3][HID * HID];         // fp16 g2w,g3w,g4w
__device__ float g_xg[BATCH * HID];
__device__ float g_xf1[BATCH * HID];
__device__ float g_xf2[BATCH * HID];

// ------------------------------ helpers ------------------------------------
__device__ __forceinline__ uint32_t smem_u32(const void* p) {
    uint32_t a;
    asm("{ .reg .u64 t; cvta.to.shared.u64 t, %1; cvt.u32.u64 %0, t; }"
        : "=r"(a) : "l"(p));
    return a;
}

__device__ __forceinline__ void ldmx4(uint32_t* r, uint32_t addr) {
    asm volatile("ldmatrix.sync.aligned.m8n8.x4.shared.b16 {%0,%1,%2,%3}, [%4];"
                 : "=r"(r[0]), "=r"(r[1]), "=r"(r[2]), "=r"(r[3]) : "r"(addr));
}

__device__ __forceinline__ void mma16816(float* d, const uint32_t* a,
                                         uint32_t b0, uint32_t b1) {
    asm volatile(
        "mma.sync.aligned.m16n8k16.row.col.f32.f16.f16.f32 "
        "{%0,%1,%2,%3}, {%4,%5,%6,%7}, {%8,%9}, {%0,%1,%2,%3};"
        : "+f"(d[0]), "+f"(d[1]), "+f"(d[2]), "+f"(d[3])
        : "r"(a[0]), "r"(a[1]), "r"(a[2]), "r"(a[3]), "r"(b0), "r"(b1));
}

#define CP_ASYNC16(dst, src) \
    asm volatile("cp.async.cg.shared.global [%0], [%1], 16;" \
                 :: "r"(dst), "l"(src) : "memory")
#define CP_COMMIT() asm volatile("cp.async.commit_group;" ::: "memory")
#define CP_WAIT1()  asm volatile("cp.async.wait_group 1;" ::: "memory")
#define CP_WAIT0()  asm volatile("cp.async.wait_group 0;" ::: "memory")

// ------- SMEM-resident conv3x3 s2 p1 + bias + relu ------------------------
__global__ __launch_bounds__(512)
void k_convsm(const float* __restrict__ in, const float* __restrict__ w,
              const float* __restrict__ bias, float* __restrict__ out,
              const float* __restrict__ statsIn, float* __restrict__ statsOut,
              const float* __restrict__ gamma, const float* __restrict__ beta,
              float cnt, int Cin, int Hin, int Hout, int ohPer)
{
    extern __shared__ float sm[];
    const int pitch = Hin + 2;                  // even -> float2-aligned rows
    const int rowsAlloc = 2 * ohPer + 1;
    const int swOff = (Cin * rowsAlloc * pitch + 3) & ~3;   // 16B-align sw
    float* sin_ = sm;                           // Cin * rowsAlloc * pitch
    float* sw = sm + swOff;                     // FS * Cin * 12
    float* sb = sw + FS * Cin * 12;             // FS
    __shared__ float sc_[FS], sh_[FS];
    __shared__ float ssum[FS], ssum2[FS];
    const int tid = threadIdx.x;
    const int n = blockIdx.x;
    const int ohBeg = blockIdx.y * ohPer;
    int ohCnt = Hout - ohBeg; if (ohCnt > ohPer) ohCnt = ohPer;

    if (tid < FS) { ssum[tid] = 0.f; ssum2[tid] = 0.f; }
    if (tid < Cin) {
        if (statsIn) {
            float mean = statsIn[tid] / cnt;
            float var = statsIn[FS + tid] / cnt - mean * mean;
            float inv = gamma[tid] * rsqrtf(var + 1e-5f);
            sc_[tid] = inv;
            sh_[tid] = beta[tid] - mean * inv;
        } else { sc_[tid] = 1.f; sh_[tid] = 0.f; }
    }
    __syncthreads();

    const int ihLoRaw = ohBeg * 2 - 1;
    const int ihLo = ihLoRaw < 0 ? 0 : ihLoRaw;
    int ihHi = (ohBeg + ohCnt - 1) * 2 + 1;
    if (ihHi > Hin - 1) ihHi = Hin - 1;
    const int nrows = ihHi - ihLo + 1;

    const int hh = Hin * Hin;
    const float* ib = in + (size_t)n * Cin * hh;
    const int loadTot = Cin * nrows * Hin;
    for (int i = tid; i < loadTot; i += 512) {
        int ci = i / (nrows * Hin);
        int rem = i - ci * nrows * Hin;
        int r = rem / Hin, c = rem - r * Hin;
        sin_[ci * rowsAlloc * pitch + r * pitch + c] =
            fmaf(ib[ci * hh + (ihLo + r) * Hin + c], sc_[ci], sh_[ci]);
    }
    for (int i = tid; i < FS * Cin * 9; i += 512)
        sw[(i / 9) * 12 + (i % 9)] = w[i];
    if (tid < FS) sb[tid] = bias[tid];
    __syncthreads();

    const int Wout = Hout;
    const int hw = Hout * Wout;
    const int nqh = (ohCnt + 3) >> 2;
    const int totalG = FS * nqh * Wout;
    float* ob = out + (size_t)n * FS * hw;

    for (int i = tid; i < totalG; i += 512) {
        int ow = i % Wout; int t = i / Wout;
        int ohg = t % nqh; int co = t / nqh;
        int oh0 = ohBeg + ohg * 4;
        int nh = ohBeg + ohCnt - oh0; if (nh > 4) nh = 4;

        float bse = sb[co];
        float s0 = bse, s1 = bse, s2 = bse, s3 = bse;
        const int ihb = oh0 * 2 - 1;
        const int iw0 = ow * 2;
        const bool w0ok = (iw0 > 0);

        for (int ci = 0; ci < Cin; ci++) {
            const float* sp = sin_ + ci * rowsAlloc * pitch;
            const float* wpb = sw + (co * Cin + ci) * 12;
            float4 wA = *reinterpret_cast<const float4*>(wpb);
            float4 wB = *reinterpret_cast<const float4*>(wpb + 4);
            float w8 = wpb[8];
            float wr[9] = { wA.x, wA.y, wA.z, wA.w, wB.x, wB.y, wB.z, wB.w, w8 };
            #pragma unroll
            for (int rr = 0; rr < 9; rr++) {
                int ih = ihb + rr;
                if (ih < 0 || ih > ihHi) continue;
                const float* rowp = sp + (ih - ihLo) * pitch;
                float2 v12 = *reinterpret_cast<const float2*>(rowp + iw0);
                float v0 = w0ok ? rowp[iw0 - 1] : 0.0f;
                float v1 = v12.x, v2 = v12.y;
                if (rr <= 2) {
                    s0 += v0 * wr[rr * 3] + v1 * wr[rr * 3 + 1] + v2 * wr[rr * 3 + 2];
                }
                if (rr >= 2 && rr <= 4) {
                    int kh = rr - 2;
                    s1 += v0 * wr[kh * 3] + v1 * wr[kh * 3 + 1] + v2 * wr[kh * 3 + 2];
                }
                if (rr >= 4 && rr <= 6) {
                    int kh = rr - 4;
                    s2 += v0 * wr[kh * 3] + v1 * wr[kh * 3 + 1] + v2 * wr[kh * 3 + 2];
                }
                if (rr >= 6) {
                    int kh = rr - 6;
                    s3 += v0 * wr[kh * 3] + v1 * wr[kh * 3 + 1] + v2 * wr[kh * 3 + 2];
                }
            }
        }
        s0 = fmaxf(s0, 0.f); s1 = fmaxf(s1, 0.f);
        s2 = fmaxf(s2, 0.f); s3 = fmaxf(s3, 0.f);

        float* op = ob + ((size_t)co * hw + oh0 * Wout + ow);
        float ls = s0, ls2 = s0 * s0;
        op[0] = s0;
        if (nh > 1) { op[Wout] = s1; ls += s1; ls2 += s1 * s1; }
        if (nh > 2) { op[2 * Wout] = s2; ls += s2; ls2 += s2 * s2; }
        if (nh > 3) { op[3 * Wout] = s3; ls += s3; ls2 += s3 * s3; }
        atomicAdd(&ssum[co], ls);
        atomicAdd(&ssum2[co], ls2);
    }
    __syncthreads();
    if (tid < FS) {
        atomicAdd(&statsOut[tid], ssum[tid]);
        atomicAdd(&statsOut[FS + tid], ssum2[tid]);
    }
}

// --------------------------- zero helpers ----------------------------------
__global__ void k_zerostats(float* s)
{
    if (threadIdx.x < 192) s[threadIdx.x] = 0.0f;
}
__global__ void k_zeroxg(float* xg)
{
    xg[blockIdx.x * HID + threadIdx.x] = 0.0f;
}

// ------------- g1 projections: one block per image -------------------------
__global__ __launch_bounds__(HID)
void k_objproj(const float* __restrict__ x4,
               const float* __restrict__ stats,
               const float* __restrict__ gamma,
               const float* __restrict__ beta,
               const float* __restrict__ g1w,
               float* __restrict__ P, float* __restrict__ Q)
{
    int b = blockIdx.x;
    int j = threadIdx.x;
    __shared__ float feat[OBJ][28];
    __shared__ float sc_[FS], sh_[FS];

    if (j < FS) {
        float cnt = (float)(BATCH * OBJ);
        float mean = stats[j] / cnt;
        float var = stats[FS + j] / cnt - mean * mean;
        float inv = gamma[j] * rsqrtf(var + 1e-5f);
        sc_[j] = inv;
        sh_[j] = beta[j] - mean * inv;
    }
    __syncthreads();
    for (int i = j; i < FS * OBJ; i += HID) {
        int jc = i / OBJ, o = i - jc * OBJ;
        feat[o][jc] = fmaf(x4[((size_t)b * FS + jc) * OBJ + o], sc_[jc], sh_[jc]);
    }
    if (j < OBJ) {
        feat[j][24] = ((j / 5) - 2) * 0.5f;
        feat[j][25] = ((j % 5) - 2) * 0.5f;
    }
    __syncthreads();

    float wr[52];
    const float* wrow = g1w + j * 63;
    #pragma unroll
    for (int c = 0; c < 52; c++) wr[c] = wrow[c];

    #pragma unroll 1
    for (int o = 0; o < OBJ; o++) {
        float p = 0.f, q = 0.f;
        #pragma unroll
        for (int c = 0; c < 26; c++) {
            float f = feat[o][c];
            p += wr[c] * f;
            q += wr[26 + c] * f;
        }
        P[((size_t)b * OBJ + o) * HID + j] = p;
        Q[((size_t)b * OBJ + o) * HID + j] = q;
    }
}

__global__ void k_qproj(const float* __restrict__ qst, const float* __restrict__ g1w,
                        const float* __restrict__ g1b, float* __restrict__ R)
{
    int b = blockIdx.x, j = threadIdx.x;
    __shared__ float qs[11];
    if (j < 11) qs[j] = qst[j * BATCH + b];
    __syncthreads();
    float s = g1b[j];
    const float* wr = g1w + j * 63 + 52;
    #pragma unroll
    for (int t = 0; t < 11; t++) s += wr[t] * qs[t];
    R[b * HID + j] = s;
}

// fp32 weight [256,256] -> fp16 copy
__global__ void k_w2h(const float* __restrict__ w, __half* __restrict__ o)
{
    int i = blockIdx.x * blockDim.x + threadIdx.x;
    if (i < HID * HID) o[i] = __float2half_rn(w[i]);
}

// ------------- fused g-stack: (P,Q,R) -> g2 -> g3 -> g4 -> pairsum ---------
// 512 threads / 16 warps, warp grid 4(M) x 4(N), warp tile 32x16.
// 12 phases (3 stages x 4 N-quarters); weight quarter (64x256 fp16) streamed
// by cp.async into double buffers, overlapped with the previous phase's MMA.
#define FSM_BIAS 0                          // 3 * 256 * 4 = 3072
#define FSM_T0   3072                       // 128 * 528 = 67584
#define FSM_T1   (FSM_T0 + 67584)           // 70656
#define FSM_W0   (FSM_T1 + 67584)           // 138240, 64*528 = 33792
#define FSM_W1   (FSM_W0 + 33792)           // 172032
#define FSM_TOT  (FSM_W1 + 33792)           // 205824

__global__ __launch_bounds__(512, 1)
void k_gchain(const __half* __restrict__ wh,
              const float* __restrict__ b2, const float* __restrict__ b3,
              const float* __restrict__ b4,
              const float* __restrict__ P, const float* __restrict__ Q,
              const float* __restrict__ R,
              float* __restrict__ xg)
{
    extern __shared__ char smem[];
    float* bs = reinterpret_cast<float*>(smem + FSM_BIAS);
    const int tid = threadIdx.x;
    const int wid = tid >> 5;
    const int lane = tid & 31;
    const size_t bm = (size_t)blockIdx.x * 128;
    const uint32_t sbase = smem_u32(smem);

    // prefetch phase 0 weights (stage 0, quarter 0) into W0 — overlaps build
    {
        const __half* src = wh;
        #pragma unroll
        for (int i = 0; i < 4; i++) {
            int idx = tid + i * 512;               // 0..2047
            int r = idx >> 5, c = idx & 31;
            CP_ASYNC16(sbase + FSM_W0 + r * 528 + c * 16, src + r * HID + c * 8);
        }
        CP_COMMIT();
    }

    if (tid < 256) {
        bs[tid] = b2[tid];
        bs[256 + tid] = b3[tid];
        bs[512 + tid] = b4[tid];
    }

    // build stage-1 input tile in T0: each thread owns 64 rows of one column
    {
        const int col = tid & 255;
        const int r0 = (tid >> 8) * 64;
        int rg0 = (int)bm + r0;
        int b = rg0 / 625;
        int rem = rg0 - b * 625;
        const float* Rb = R + (size_t)b * HID;
        #pragma unroll 4
        for (int r = r0; r < r0 + 64; r++) {
            int a_ = rem / 25;
            int cc = rem - a_ * 25;
            float v = P[((size_t)b * OBJ + cc) * HID + col]
                    + Q[((size_t)b * OBJ + a_) * HID + col]
                    + Rb[col];
            *reinterpret_cast<__half*>(smem + FSM_T0 + r * 528 + col * 2) =
                __float2half_rn(fmaxf(v, 0.0f));
            rem++;
            if (rem == 625) { rem = 0; b++; Rb = R + (size_t)b * HID; }
        }
    }

    const int warp_m = (wid & 3) * 32;
    const int warp_n = (wid >> 2) * 16;      // local col within 64-quarter
    uint32_t aoff[2];
    #pragma unroll
    for (int mt = 0; mt < 2; mt++) {
        int row = warp_m + mt * 16 + (lane & 15);
        aoff[mt] = row * 528 + (lane >> 4) * 16;
    }
    const uint32_t boff =
        (uint32_t)(warp_n + ((lane >> 4) * 8) + (lane & 7)) * 528 +
        ((lane >> 3) & 1) * 16;

    int inOff = FSM_T0, outOff = FSM_T1;
    int p = 0;
    #pragma unroll 1
    for (int stage = 0; stage < 3; stage++) {
        const float* sbias = bs + stage * 256;
        #pragma unroll 1
        for (int q = 0; q < 4; q++, p++) {
            __syncthreads();   // pass p-1 done (buffers free); tile ready at p=0
            if (p + 1 < 12) {
                int ns = (p + 1) >> 2, nq = (p + 1) & 3;
                const __half* src = wh + (size_t)ns * HID * HID + nq * 64 * HID;
                uint32_t dstBase = sbase + (((p + 1) & 1) ? FSM_W1 : FSM_W0);
                #pragma unroll
                for (int i = 0; i < 4; i++) {
                    int idx = tid + i * 512;
                    int r = idx >> 5, c = idx & 31;
                    CP_ASYNC16(dstBase + r * 528 + c * 16, src + r * HID + c * 8);
                }
                CP_COMMIT();
                CP_WAIT1();    // phase p's group complete, p+1 in flight
            } else {
                CP_WAIT0();
            }
            __syncthreads();   // all threads see weight buffer p

            const uint32_t wBuf = sbase + ((p & 1) ? FSM_W1 : FSM_W0);
            const uint32_t b_addr = wBuf + boff;

            float acc[2][2][4];
            #pragma unroll
            for (int mt = 0; mt < 2; mt++)
                #pragma unroll
                for (int nt = 0; nt < 2; nt++)
                    #pragma unroll
                    for (int qq = 0; qq < 4; qq++) acc[mt][nt][qq] = 0.f;

            const uint32_t hInBase = sbase + inOff;
            #pragma unroll
            for (int ks = 0; ks < 16; ks++) {
                uint32_t a[2][4], b[4];
                #pragma unroll
                for (int mt = 0; mt < 2; mt++)
                    ldmx4(a[mt], hInBase + aoff[mt] + ks * 32);
                ldmx4(b, b_addr + ks * 32);
                #pragma unroll
                for (int mt = 0; mt < 2; mt++)
                    #pragma unroll
                    for (int nt = 0; nt < 2; nt++)
                        mma16816(acc[mt][nt], a[mt], b[nt * 2], b[nt * 2 + 1]);
            }

            // epilogue: bias + relu -> fp16 into hOut at cols q*64+...
            #pragma unroll
            for (int mt = 0; mt < 2; mt++) {
                int r0 = warp_m + mt * 16 + (lane >> 2);
                #pragma unroll
                for (int nt = 0; nt < 2; nt++) {
                    int c0 = q * 64 + warp_n + nt * 8 + (lane & 3) * 2;
                    float bb0 = sbias[c0], bb1 = sbias[c0 + 1];
                    float v0 = fmaxf(acc[mt][nt][0] + bb0, 0.f);
                    float v1 = fmaxf(acc[mt][nt][1] + bb1, 0.f);
                    float v2 = fmaxf(acc[mt][nt][2] + bb0, 0.f);
                    float v3 = fmaxf(acc[mt][nt][3] + bb1, 0.f);
                    __half2 p01 = __floats2half2_rn(v0, v1);
                    __half2 p23 = __floats2half2_rn(v2, v3);
                    *reinterpret_cast<uint32_t*>(smem + outOff + r0 * 528 + c0 * 2) =
                        *reinterpret_cast<uint32_t*>(&p01);
                    *reinterpret_cast<uint32_t*>(smem + outOff + (r0 + 8) * 528 + c0 * 2) =
                        *reinterpret_cast<uint32_t*>(&p23);
                }
            }
        }
        int t = inOff; inOff = outOff; outOff = t;
    }

    __syncthreads();
    // pairsum over the final tile (in inOff after the last swap)
    {
        const int col = tid & 255;
        const int r0 = (tid >> 8) * 64;
        int rg0 = (int)bm + r0;
        int b = rg0 / 625;
        int rem = rg0 - b * 625;
        float s = 0.f;
        const char* hb = smem + inOff;
        #pragma unroll 4
        for (int r = r0; r < r0 + 64; r++) {
            s += __half2float(*reinterpret_cast<const __half*>(hb + r * 528 + col * 2));
            rem++;
            if (rem == 625) {
                atomicAdd(&xg[b * HID + col], s);
                s = 0.f; rem = 0; b++;
            }
        }
        if (rem > 0) atomicAdd(&xg[b * HID + col], s);
    }
}

// ---------------- fp32 SGEMM for f-layers (small M) ------------------------
__global__ __launch_bounds__(256) void k_gemm256(const float* __restrict__ A,
    const float* __restrict__ W, const float* __restrict__ bias,
    float* __restrict__ C, int M, int doRelu)
{
    __shared__ float As[8][128];
    __shared__ float Bs[8][128];
    const int tid = threadIdx.x;
    const int bm = blockIdx.x * 128;
    const int bn = blockIdx.y * 128;
    const int tx = tid & 15;
    const int ty = tid >> 4;

    float acc[8][8];
    #pragma unroll
    for (int i = 0; i < 8; i++)
        #pragma unroll
        for (int j = 0; j < 8; j++) acc[i][j] = 0.f;

    const int lrow = tid >> 1;
    const int lk = (tid & 1) * 4;
    const float* Ag = A + (size_t)(bm + lrow) * 256 + lk;
    const float* Wg = W + (size_t)(bn + lrow) * 256 + lk;

    for (int k0 = 0; k0 < 256; k0 += 8) {
        float4 av = *reinterpret_cast<const float4*>(Ag + k0);
        float4 wv = *reinterpret_cast<const float4*>(Wg + k0);
        As[lk + 0][lrow] = av.x; As[lk + 1][lrow] = av.y;
        As[lk + 2][lrow] = av.z; As[lk + 3][lrow] = av.w;
        Bs[lk + 0][lrow] = wv.x; Bs[lk + 1][lrow] = wv.y;
        Bs[lk + 2][lrow] = wv.z; Bs[lk + 3][lrow] = wv.w;
        __syncthreads();
        #pragma unroll
        for (int kk = 0; kk < 8; kk++) {
            float a[8], b[8];
            *reinterpret_cast<float4*>(&a[0]) = *reinterpret_cast<const float4*>(&As[kk][ty * 8]);
            *reinterpret_cast<float4*>(&a[4]) = *reinterpret_cast<const float4*>(&As[kk][ty * 8 + 4]);
            *reinterpret_cast<float4*>(&b[0]) = *reinterpret_cast<const float4*>(&Bs[kk][tx * 8]);
            *reinterpret_cast<float4*>(&b[4]) = *reinterpret_cast<const float4*>(&Bs[kk][tx * 8 + 4]);
            #pragma unroll
            for (int i = 0; i < 8; i++)
                #pragma unroll
                for (int j = 0; j < 8; j++)
                    acc[i][j] += a[i] * b[j];
        }
        __syncthreads();
    }

    #pragma unroll
    for (int i = 0; i < 8; i++) {
        size_t row = (size_t)(bm + ty * 8 + i);
        #pragma unroll
        for (int j = 0; j < 8; j += 4) {
            int col = bn + tx * 8 + j;
            float4 v;
            v.x = acc[i][j + 0] + bias[col + 0];
            v.y = acc[i][j + 1] + bias[col + 1];
            v.z = acc[i][j + 2] + bias[col + 2];
            v.w = acc[i][j + 3] + bias[col + 3];
            if (doRelu) {
                v.x = fmaxf(v.x, 0.f); v.y = fmaxf(v.y, 0.f);
                v.z = fmaxf(v.z, 0.f); v.w = fmaxf(v.w, 0.f);
            }
            *reinterpret_cast<float4*>(&C[row * 256 + col]) = v;
        }
    }
}

// -------------------- fc3 (256->10) + log_softmax --------------------------
__global__ void k_final(const float* __restrict__ xf, const float* __restrict__ w,
                        const float* __restrict__ bias, float* __restrict__ out)
{
    int b = blockIdx.x;
    __shared__ float xs[HID];
    __shared__ float logits[10];
    xs[threadIdx.x] = xf[b * HID + threadIdx.x];
    __syncthreads();
    if (threadIdx.x < 10) {
        float s = bias[threadIdx.x];
        const float* wr = w + threadIdx.x * HID;
        for (int c = 0; c < HID; c++) s += wr[c] * xs[c];
        logits[threadIdx.x] = s;
    }
    __syncthreads();
    if (threadIdx.x == 0) {
        float mx = -1e30f;
        for (int n = 0; n < 10; n++) mx = fmaxf(mx, logits[n]);
        float se = 0.f;
        for (int n = 0; n < 10; n++) se += expf(logits[n] - mx);
        float lse = logf(se) + mx;
        for (int n = 0; n < 10; n++) out[b * 10 + n] = logits[n] - lse;
    }
}

// ---------------------------------------------------------------------------
static void* sym(const void* devSymbol)
{
    void* p = nullptr;
    cudaGetSymbolAddress(&p, devSymbol);
    return p;
}

static int conv_smem(int Cin, int Hin, int ohPer)
{
    int pitch = Hin + 2;
    int rowsAlloc = 2 * ohPer + 1;
    int swOff = (Cin * rowsAlloc * pitch + 3) & ~3;
    return (swOff + FS * Cin * 12 + FS) * 4;
}

extern "C" void kernel_launch(void* const* d_in, const int* in_sizes, int n_in,
                              void* d_out, int out_size)
{
    const float* img  = (const float*)d_in[0];
    const float* qst  = (const float*)d_in[1];
    const float* cw[4] = { (const float*)d_in[2],  (const float*)d_in[6],
                           (const float*)d_in[10], (const float*)d_in[14] };
    const float* cb[4] = { (const float*)d_in[3],  (const float*)d_in[7],
                           (const float*)d_in[11], (const float*)d_in[15] };
    const float* bg[4] = { (const float*)d_in[4],  (const float*)d_in[8],
                           (const float*)d_in[12], (const float*)d_in[16] };
    const float* bb[4] = { (const float*)d_in[5],  (const float*)d_in[9],
                           (const float*)d_in[13], (const float*)d_in[17] };
    const float* g1w = (const float*)d_in[18]; const float* g1b = (const float*)d_in[19];
    const float* g2w = (const float*)d_in[20]; const float* g2b = (const float*)d_in[21];
    const float* g3w = (const float*)d_in[22]; const float* g3b = (const float*)d_in[23];
    const float* g4w = (const float*)d_in[24]; const float* g4b = (const float*)d_in[25];
    const float* f1w = (const float*)d_in[26]; const float* f1b = (const float*)d_in[27];
    const float* fc2w = (const float*)d_in[28]; const float* fc2b = (const float*)d_in[29];
    const float* fc3w = (const float*)d_in[30]; const float* fc3b = (const float*)d_in[31];

    float* c1 = (float*)sym(g_c1); float* c2 = (float*)sym(g_c2);
    float* c3 = (float*)sym(g_c3); float* c4 = (float*)sym(g_c4);
    float* st = (float*)sym(g_stats4);
    float* P = (float*)sym(g_P); float* Q = (float*)sym(g_Q); float* R = (float*)sym(g_R);
    __half* wh = (__half*)sym(g_wh);
    float* xg = (float*)sym(g_xg); float* xf1 = (float*)sym(g_xf1); float* xf2 = (float*)sym(g_xf2);
    float* out = (float*)d_out;

    int sm1 = conv_smem(3, 80, 10);     // L1 split 4
    int sm2 = conv_smem(FS, 40, 10);    // L2 split 2
    int sm3 = conv_smem(FS, 20, 5);     // L3 split 2
    int sm4 = conv_smem(FS, 10, 5);     // L4 full
    int smMax = sm1;
    if (sm2 > smMax) smMax = sm2;
    if (sm3 > smMax) smMax = sm3;
    if (sm4 > smMax) smMax = sm4;

    cudaFuncSetAttribute(k_gchain, cudaFuncAttributeMaxDynamicSharedMemorySize, FSM_TOT);
    cudaFuncSetAttribute(k_convsm, cudaFuncAttributeMaxDynamicSharedMemorySize, smMax);

    k_zerostats<<<1, 192>>>(st);
    k_zeroxg<<<BATCH, HID>>>(xg);

    // ---- conv stack (row-split CTAs) ----
    k_convsm<<<dim3(BATCH, 4), 512, sm1>>>(img, cw[0], cb[0], c1,
                                           nullptr, st + 0 * 48, nullptr, nullptr,
                                           0.f, 3, 80, 40, 10);
    k_convsm<<<dim3(BATCH, 2), 512, sm2>>>(c1, cw[1], cb[1], c2,
                                           st + 0 * 48, st + 1 * 48, bg[0], bb[0],
                                           (float)(BATCH * 1600), FS, 40, 20, 10);
    k_convsm<<<dim3(BATCH, 2), 512, sm3>>>(c2, cw[2], cb[2], c3,
                                           st + 1 * 48, st + 2 * 48, bg[1], bb[1],
                                           (float)(BATCH * 400), FS, 20, 10, 5);
    k_convsm<<<dim3(BATCH, 1), 512, sm4>>>(c3, cw[3], cb[3], c4,
                                           st + 2 * 48, st + 3 * 48, bg[2], bb[2],
                                           (float)(BATCH * 100), FS, 10, 5, 5);

    // fp16 weight copies
    k_w2h<<<(HID * HID + 255) / 256, 256>>>(g2w, wh);
    k_w2h<<<(HID * HID + 255) / 256, 256>>>(g3w, wh + HID * HID);
    k_w2h<<<(HID * HID + 255) / 256, 256>>>(g4w, wh + 2 * HID * HID);

    // g1 projections (BN4 applied inside objproj)
    k_objproj<<<BATCH, HID>>>(c4, st + 3 * 48, bg[3], bb[3], g1w, P, Q);
    k_qproj<<<BATCH, HID>>>(qst, g1w, g1b, R);

    // fused g2->g3->g4->pairsum (512 threads, cp.async weight pipeline)
    k_gchain<<<NPAIR / 128, 512, FSM_TOT>>>(wh, g2b, g3b, g4b, P, Q, R, xg);

    // f layers (fp32)
    dim3 gsmall(BATCH / 128, 2);
    k_gemm256<<<gsmall, 256>>>(xg, f1w, f1b, xf1, BATCH, 1);
    k_gemm256<<<gsmall, 256>>>(xf1, fc2w, fc2b, xf2, BATCH, 1);

    // fc3 + log_softmax
    k_final<<<BATCH, HID>>>(xf2, fc3w, fc3b, out);
}

// round 16
// speedup vs baseline: 1.0485x; 1.0485x over previous
#include <cuda_runtime.h>
#include <cuda_fp16.h>
#include <cstdint>
#include <math.h>

// ---------------------------------------------------------------------------
// RelNet forward.
// conv stack: SMEM-resident conv3x3 s2 (+bias+relu), BN(prev) folded into
// load, BN stats(this) fused in epilogue. Row-splits: L1 x4, L2 x2, L3 x2
// (measured-best combo). Vectorized smem reads; 4-wide OH register blocking.
// g-stack: ONE fused kernel per 128 pair-rows, 512 threads / 16 warps,
//   warp grid 4x4 (tile 32x32), 2 N-half passes, synchronous weight loads
//   (R14 version — measured faster than the cp.async 12-phase variant):
//   A=relu(P+Q+R) -> g2 -> g3 -> g4 -> pairsum, all tiles in SMEM,
//   fp16 HMMA (mma.sync m16n8k16, fp32 accum), pairsum -> fp32 atomics.
// objproj: one block per image, g1w rows cached in registers (25x reuse).
// f1,fc2 fp32 SGEMM -> fc3 + log_softmax.
// tcgen05 unavailable: harness PTX targets baseline sm_103 which rejects it.
// ---------------------------------------------------------------------------

#define BATCH 512
#define FS 24
#define OBJ 25
#define HID 256
#define NPAIR (BATCH * OBJ * OBJ)   // 320000

// ------------------------- scratch (static device) -------------------------
__device__ float g_c1[BATCH * FS * 40 * 40];
__device__ float g_c2[BATCH * FS * 20 * 20];
__device__ float g_c3[BATCH * FS * 10 * 10];
__device__ float g_c4[BATCH * FS * 5 * 5];
__device__ float g_stats4[4][48];             // per-layer BN stats (sum, sumsq)
__device__ float g_P[BATCH * OBJ * HID];
__device__ float g_Q[BATCH * OBJ * HID];
__device__ float g_R[BATCH * HID];
__device__ __half g_wh[3][HID * HID];         // fp16 g2w,g3w,g4w
__device__ float g_xg[BATCH * HID];
__device__ float g_xf1[BATCH * HID];
__device__ float g_xf2[BATCH * HID];

// ------------------------------ helpers ------------------------------------
__device__ __forceinline__ uint32_t smem_u32(const void* p) {
    uint32_t a;
    asm("{ .reg .u64 t; cvta.to.shared.u64 t, %1; cvt.u32.u64 %0, t; }"
        : "=r"(a) : "l"(p));
    return a;
}

__device__ __forceinline__ void ldmx4(uint32_t* r, uint32_t addr) {
    asm volatile("ldmatrix.sync.aligned.m8n8.x4.shared.b16 {%0,%1,%2,%3}, [%4];"
                 : "=r"(r[0]), "=r"(r[1]), "=r"(r[2]), "=r"(r[3]) : "r"(addr));
}

__device__ __forceinline__ void mma16816(float* d, const uint32_t* a,
                                         uint32_t b0, uint32_t b1) {
    asm volatile(
        "mma.sync.aligned.m16n8k16.row.col.f32.f16.f16.f32 "
        "{%0,%1,%2,%3}, {%4,%5,%6,%7}, {%8,%9}, {%0,%1,%2,%3};"
        : "+f"(d[0]), "+f"(d[1]), "+f"(d[2]), "+f"(d[3])
        : "r"(a[0]), "r"(a[1]), "r"(a[2]), "r"(a[3]), "r"(b0), "r"(b1));
}

// ------- SMEM-resident conv3x3 s2 p1 + bias + relu ------------------------
__global__ __launch_bounds__(512)
void k_convsm(const float* __restrict__ in, const float* __restrict__ w,
              const float* __restrict__ bias, float* __restrict__ out,
              const float* __restrict__ statsIn, float* __restrict__ statsOut,
              const float* __restrict__ gamma, const float* __restrict__ beta,
              float cnt, int Cin, int Hin, int Hout, int ohPer)
{
    extern __shared__ float sm[];
    const int pitch = Hin + 2;                  // even -> float2-aligned rows
    const int rowsAlloc = 2 * ohPer + 1;
    const int swOff = (Cin * rowsAlloc * pitch + 3) & ~3;   // 16B-align sw
    float* sin_ = sm;                           // Cin * rowsAlloc * pitch
    float* sw = sm + swOff;                     // FS * Cin * 12
    float* sb = sw + FS * Cin * 12;             // FS
    __shared__ float sc_[FS], sh_[FS];
    __shared__ float ssum[FS], ssum2[FS];
    const int tid = threadIdx.x;
    const int n = blockIdx.x;
    const int ohBeg = blockIdx.y * ohPer;
    int ohCnt = Hout - ohBeg; if (ohCnt > ohPer) ohCnt = ohPer;

    if (tid < FS) { ssum[tid] = 0.f; ssum2[tid] = 0.f; }
    if (tid < Cin) {
        if (statsIn) {
            float mean = statsIn[tid] / cnt;
            float var = statsIn[FS + tid] / cnt - mean * mean;
            float inv = gamma[tid] * rsqrtf(var + 1e-5f);
            sc_[tid] = inv;
            sh_[tid] = beta[tid] - mean * inv;
        } else { sc_[tid] = 1.f; sh_[tid] = 0.f; }
    }
    __syncthreads();

    const int ihLoRaw = ohBeg * 2 - 1;
    const int ihLo = ihLoRaw < 0 ? 0 : ihLoRaw;
    int ihHi = (ohBeg + ohCnt - 1) * 2 + 1;
    if (ihHi > Hin - 1) ihHi = Hin - 1;
    const int nrows = ihHi - ihLo + 1;

    const int hh = Hin * Hin;
    const float* ib = in + (size_t)n * Cin * hh;
    const int loadTot = Cin * nrows * Hin;
    for (int i = tid; i < loadTot; i += 512) {
        int ci = i / (nrows * Hin);
        int rem = i - ci * nrows * Hin;
        int r = rem / Hin, c = rem - r * Hin;
        sin_[ci * rowsAlloc * pitch + r * pitch + c] =
            fmaf(ib[ci * hh + (ihLo + r) * Hin + c], sc_[ci], sh_[ci]);
    }
    for (int i = tid; i < FS * Cin * 9; i += 512)
        sw[(i / 9) * 12 + (i % 9)] = w[i];
    if (tid < FS) sb[tid] = bias[tid];
    __syncthreads();

    const int Wout = Hout;
    const int hw = Hout * Wout;
    const int nqh = (ohCnt + 3) >> 2;
    const int totalG = FS * nqh * Wout;
    float* ob = out + (size_t)n * FS * hw;

    for (int i = tid; i < totalG; i += 512) {
        int ow = i % Wout; int t = i / Wout;
        int ohg = t % nqh; int co = t / nqh;
        int oh0 = ohBeg + ohg * 4;
        int nh = ohBeg + ohCnt - oh0; if (nh > 4) nh = 4;

        float bse = sb[co];
        float s0 = bse, s1 = bse, s2 = bse, s3 = bse;
        const int ihb = oh0 * 2 - 1;
        const int iw0 = ow * 2;
        const bool w0ok = (iw0 > 0);

        for (int ci = 0; ci < Cin; ci++) {
            const float* sp = sin_ + ci * rowsAlloc * pitch;
            const float* wpb = sw + (co * Cin + ci) * 12;
            float4 wA = *reinterpret_cast<const float4*>(wpb);
            float4 wB = *reinterpret_cast<const float4*>(wpb + 4);
            float w8 = wpb[8];
            float wr[9] = { wA.x, wA.y, wA.z, wA.w, wB.x, wB.y, wB.z, wB.w, w8 };
            #pragma unroll
            for (int rr = 0; rr < 9; rr++) {
                int ih = ihb + rr;
                if (ih < 0 || ih > ihHi) continue;
                const float* rowp = sp + (ih - ihLo) * pitch;
                float2 v12 = *reinterpret_cast<const float2*>(rowp + iw0);
                float v0 = w0ok ? rowp[iw0 - 1] : 0.0f;
                float v1 = v12.x, v2 = v12.y;
                if (rr <= 2) {
                    s0 += v0 * wr[rr * 3] + v1 * wr[rr * 3 + 1] + v2 * wr[rr * 3 + 2];
                }
                if (rr >= 2 && rr <= 4) {
                    int kh = rr - 2;
                    s1 += v0 * wr[kh * 3] + v1 * wr[kh * 3 + 1] + v2 * wr[kh * 3 + 2];
                }
                if (rr >= 4 && rr <= 6) {
                    int kh = rr - 4;
                    s2 += v0 * wr[kh * 3] + v1 * wr[kh * 3 + 1] + v2 * wr[kh * 3 + 2];
                }
                if (rr >= 6) {
                    int kh = rr - 6;
                    s3 += v0 * wr[kh * 3] + v1 * wr[kh * 3 + 1] + v2 * wr[kh * 3 + 2];
                }
            }
        }
        s0 = fmaxf(s0, 0.f); s1 = fmaxf(s1, 0.f);
        s2 = fmaxf(s2, 0.f); s3 = fmaxf(s3, 0.f);

        float* op = ob + ((size_t)co * hw + oh0 * Wout + ow);
        float ls = s0, ls2 = s0 * s0;
        op[0] = s0;
        if (nh > 1) { op[Wout] = s1; ls += s1; ls2 += s1 * s1; }
        if (nh > 2) { op[2 * Wout] = s2; ls += s2; ls2 += s2 * s2; }
        if (nh > 3) { op[3 * Wout] = s3; ls += s3; ls2 += s3 * s3; }
        atomicAdd(&ssum[co], ls);
        atomicAdd(&ssum2[co], ls2);
    }
    __syncthreads();
    if (tid < FS) {
        atomicAdd(&statsOut[tid], ssum[tid]);
        atomicAdd(&statsOut[FS + tid], ssum2[tid]);
    }
}

// --------------------------- zero helpers ----------------------------------
__global__ void k_zerostats(float* s)
{
    if (threadIdx.x < 192) s[threadIdx.x] = 0.0f;
}
__global__ void k_zeroxg(float* xg)
{
    xg[blockIdx.x * HID + threadIdx.x] = 0.0f;
}

// ------------- g1 projections: one block per image -------------------------
__global__ __launch_bounds__(HID)
void k_objproj(const float* __restrict__ x4,
               const float* __restrict__ stats,
               const float* __restrict__ gamma,
               const float* __restrict__ beta,
               const float* __restrict__ g1w,
               float* __restrict__ P, float* __restrict__ Q)
{
    int b = blockIdx.x;
    int j = threadIdx.x;
    __shared__ float feat[OBJ][28];
    __shared__ float sc_[FS], sh_[FS];

    if (j < FS) {
        float cnt = (float)(BATCH * OBJ);
        float mean = stats[j] / cnt;
        float var = stats[FS + j] / cnt - mean * mean;
        float inv = gamma[j] * rsqrtf(var + 1e-5f);
        sc_[j] = inv;
        sh_[j] = beta[j] - mean * inv;
    }
    __syncthreads();
    for (int i = j; i < FS * OBJ; i += HID) {
        int jc = i / OBJ, o = i - jc * OBJ;
        feat[o][jc] = fmaf(x4[((size_t)b * FS + jc) * OBJ + o], sc_[jc], sh_[jc]);
    }
    if (j < OBJ) {
        feat[j][24] = ((j / 5) - 2) * 0.5f;
        feat[j][25] = ((j % 5) - 2) * 0.5f;
    }
    __syncthreads();

    float wr[52];
    const float* wrow = g1w + j * 63;
    #pragma unroll
    for (int c = 0; c < 52; c++) wr[c] = wrow[c];

    #pragma unroll 1
    for (int o = 0; o < OBJ; o++) {
        float p = 0.f, q = 0.f;
        #pragma unroll
        for (int c = 0; c < 26; c++) {
            float f = feat[o][c];
            p += wr[c] * f;
            q += wr[26 + c] * f;
        }
        P[((size_t)b * OBJ + o) * HID + j] = p;
        Q[((size_t)b * OBJ + o) * HID + j] = q;
    }
}

__global__ void k_qproj(const float* __restrict__ qst, const float* __restrict__ g1w,
                        const float* __restrict__ g1b, float* __restrict__ R)
{
    int b = blockIdx.x, j = threadIdx.x;
    __shared__ float qs[11];
    if (j < 11) qs[j] = qst[j * BATCH + b];
    __syncthreads();
    float s = g1b[j];
    const float* wr = g1w + j * 63 + 52;
    #pragma unroll
    for (int t = 0; t < 11; t++) s += wr[t] * qs[t];
    R[b * HID + j] = s;
}

// fp32 weight [256,256] -> fp16 copy
__global__ void k_w2h(const float* __restrict__ w, __half* __restrict__ o)
{
    int i = blockIdx.x * blockDim.x + threadIdx.x;
    if (i < HID * HID) o[i] = __float2half_rn(w[i]);
}

// ------------- fused g-stack: (P,Q,R) -> g2 -> g3 -> g4 -> pairsum ---------
// 512 threads / 16 warps, warp grid 4(M) x 4(N), warp tile 32x32 (R14 best).
#define FSM_BIAS 0                          // 3 * 256 * 4 = 3072
#define FSM_T0   3072                       // 128 * 528 = 67584
#define FSM_T1   (FSM_T0 + 67584)           // 70656
#define FSM_W    (FSM_T1 + 67584)           // 138240
#define FSM_TOT  (FSM_W + 67584)            // 205824

__global__ __launch_bounds__(512, 1)
void k_gchain(const __half* __restrict__ wh,
              const float* __restrict__ b2, const float* __restrict__ b3,
              const float* __restrict__ b4,
              const float* __restrict__ P, const float* __restrict__ Q,
              const float* __restrict__ R,
              float* __restrict__ xg)
{
    extern __shared__ char smem[];
    float* bs = reinterpret_cast<float*>(smem + FSM_BIAS);
    uint4* sW = reinterpret_cast<uint4*>(smem + FSM_W);
    const int tid = threadIdx.x;
    const int wid = tid >> 5;
    const int lane = tid & 31;
    const size_t bm = (size_t)blockIdx.x * 128;

    if (tid < 256) {
        bs[tid] = b2[tid];
        bs[256 + tid] = b3[tid];
        bs[512 + tid] = b4[tid];
    }

    // build stage-1 input tile in T0: each thread owns 64 rows of one column
    {
        const int col = tid & 255;
        const int r0 = (tid >> 8) * 64;
        int rg0 = (int)bm + r0;
        int b = rg0 / 625;
        int rem = rg0 - b * 625;
        const float* Rb = R + (size_t)b * HID;
        #pragma unroll 4
        for (int r = r0; r < r0 + 64; r++) {
            int a_ = rem / 25;
            int cc = rem - a_ * 25;
            float v = P[((size_t)b * OBJ + cc) * HID + col]
                    + Q[((size_t)b * OBJ + a_) * HID + col]
                    + Rb[col];
            *reinterpret_cast<__half*>(smem + FSM_T0 + r * 528 + col * 2) =
                __float2half_rn(fmaxf(v, 0.0f));
            rem++;
            if (rem == 625) { rem = 0; b++; Rb = R + (size_t)b * HID; }
        }
    }

    const int warp_m = (wid & 3) * 32;
    const int warp_n = ((wid >> 2) & 3) * 32;    // local col within 128-half
    const uint32_t sWa = smem_u32(smem + FSM_W);

    uint32_t aoff[2], b_addr[2];
    #pragma unroll
    for (int mt = 0; mt < 2; mt++) {
        int row = warp_m + mt * 16 + (lane & 15);
        aoff[mt] = row * 528 + (lane >> 4) * 16;
    }
    #pragma unroll
    for (int nt2 = 0; nt2 < 2; nt2++) {
        int row = warp_n + nt2 * 16 + ((lane >> 4) * 8) + (lane & 7);
        b_addr[nt2] = sWa + row * 528 + ((lane >> 3) & 1) * 16;
    }

    int inOff = FSM_T0, outOff = FSM_T1;
    #pragma unroll 1
    for (int stage = 0; stage < 3; stage++) {
        const float* sbias = bs + stage * 256;
        #pragma unroll 1
        for (int nn = 0; nn < 2; nn++) {
            __syncthreads();   // prev pass done with W; hIn writes visible
            const uint4* Wg = reinterpret_cast<const uint4*>(
                wh + (size_t)stage * HID * HID + nn * 128 * HID);
            #pragma unroll
            for (int i = 0; i < 8; i++) {
                int idx = tid + i * 512;
                sW[(idx >> 5) * 33 + (idx & 31)] = Wg[idx];
            }
            __syncthreads();

            float acc[2][4][4];
            #pragma unroll
            for (int mt = 0; mt < 2; mt++)
                #pragma unroll
                for (int nt = 0; nt < 4; nt++)
                    #pragma unroll
                    for (int q = 0; q < 4; q++) acc[mt][nt][q] = 0.f;

            const uint32_t hInBase = smem_u32(smem + inOff);
            #pragma unroll
            for (int ks = 0; ks < 16; ks++) {
                uint32_t a[2][4], b[2][4];
                #pragma unroll
                for (int mt = 0; mt < 2; mt++)
                    ldmx4(a[mt], hInBase + aoff[mt] + ks * 32);
                #pragma unroll
                for (int nt2 = 0; nt2 < 2; nt2++)
                    ldmx4(b[nt2], b_addr[nt2] + ks * 32);
                #pragma unroll
                for (int mt = 0; mt < 2; mt++)
                    #pragma unroll
                    for (int nt = 0; nt < 4; nt++)
                        mma16816(acc[mt][nt], a[mt],
                                 b[nt >> 1][(nt & 1) * 2],
                                 b[nt >> 1][(nt & 1) * 2 + 1]);
            }

            // epilogue: bias + relu -> fp16 into hOut at cols nn*128+...
            #pragma unroll
            for (int mt = 0; mt < 2; mt++) {
                int r0 = warp_m + mt * 16 + (lane >> 2);
                #pragma unroll
                for (int nt = 0; nt < 4; nt++) {
                    int c0 = nn * 128 + warp_n + nt * 8 + (lane & 3) * 2;
                    float bb0 = sbias[c0], bb1 = sbias[c0 + 1];
                    float v0 = fmaxf(acc[mt][nt][0] + bb0, 0.f);
                    float v1 = fmaxf(acc[mt][nt][1] + bb1, 0.f);
                    float v2 = fmaxf(acc[mt][nt][2] + bb0, 0.f);
                    float v3 = fmaxf(acc[mt][nt][3] + bb1, 0.f);
                    __half2 p01 = __floats2half2_rn(v0, v1);
                    __half2 p23 = __floats2half2_rn(v2, v3);
                    *reinterpret_cast<uint32_t*>(smem + outOff + r0 * 528 + c0 * 2) =
                        *reinterpret_cast<uint32_t*>(&p01);
                    *reinterpret_cast<uint32_t*>(smem + outOff + (r0 + 8) * 528 + c0 * 2) =
                        *reinterpret_cast<uint32_t*>(&p23);
                }
            }
        }
        int t = inOff; inOff = outOff; outOff = t;
    }

    __syncthreads();
    // pairsum over the final tile (in inOff after the last swap)
    {
        const int col = tid & 255;
        const int r0 = (tid >> 8) * 64;
        int rg0 = (int)bm + r0;
        int b = rg0 / 625;
        int rem = rg0 - b * 625;
        float s = 0.f;
        const char* hb = smem + inOff;
        #pragma unroll 4
        for (int r = r0; r < r0 + 64; r++) {
            s += __half2float(*reinterpret_cast<const __half*>(hb + r * 528 + col * 2));
            rem++;
            if (rem == 625) {
                atomicAdd(&xg[b * HID + col], s);
                s = 0.f; rem = 0; b++;
            }
        }
        if (rem > 0) atomicAdd(&xg[b * HID + col], s);
    }
}

// ---------------- fp32 SGEMM for f-layers (small M) ------------------------
__global__ __launch_bounds__(256) void k_gemm256(const float* __restrict__ A,
    const float* __restrict__ W, const float* __restrict__ bias,
    float* __restrict__ C, int M, int doRelu)
{
    __shared__ float As[8][128];
    __shared__ float Bs[8][128];
    const int tid = threadIdx.x;
    const int bm = blockIdx.x * 128;
    const int bn = blockIdx.y * 128;
    const int tx = tid & 15;
    const int ty = tid >> 4;

    float acc[8][8];
    #pragma unroll
    for (int i = 0; i < 8; i++)
        #pragma unroll
        for (int j = 0; j < 8; j++) acc[i][j] = 0.f;

    const int lrow = tid >> 1;
    const int lk = (tid & 1) * 4;
    const float* Ag = A + (size_t)(bm + lrow) * 256 + lk;
    const float* Wg = W + (size_t)(bn + lrow) * 256 + lk;

    for (int k0 = 0; k0 < 256; k0 += 8) {
        float4 av = *reinterpret_cast<const float4*>(Ag + k0);
        float4 wv = *reinterpret_cast<const float4*>(Wg + k0);
        As[lk + 0][lrow] = av.x; As[lk + 1][lrow] = av.y;
        As[lk + 2][lrow] = av.z; As[lk + 3][lrow] = av.w;
        Bs[lk + 0][lrow] = wv.x; Bs[lk + 1][lrow] = wv.y;
        Bs[lk + 2][lrow] = wv.z; Bs[lk + 3][lrow] = wv.w;
        __syncthreads();
        #pragma unroll
        for (int kk = 0; kk < 8; kk++) {
            float a[8], b[8];
            *reinterpret_cast<float4*>(&a[0]) = *reinterpret_cast<const float4*>(&As[kk][ty * 8]);
            *reinterpret_cast<float4*>(&a[4]) = *reinterpret_cast<const float4*>(&As[kk][ty * 8 + 4]);
            *reinterpret_cast<float4*>(&b[0]) = *reinterpret_cast<const float4*>(&Bs[kk][tx * 8]);
            *reinterpret_cast<float4*>(&b[4]) = *reinterpret_cast<const float4*>(&Bs[kk][tx * 8 + 4]);
            #pragma unroll
            for (int i = 0; i < 8; i++)
                #pragma unroll
                for (int j = 0; j < 8; j++)
                    acc[i][j] += a[i] * b[j];
        }
        __syncthreads();
    }

    #pragma unroll
    for (int i = 0; i < 8; i++) {
        size_t row = (size_t)(bm + ty * 8 + i);
        #pragma unroll
        for (int j = 0; j < 8; j += 4) {
            int col = bn + tx * 8 + j;
            float4 v;
            v.x = acc[i][j + 0] + bias[col + 0];
            v.y = acc[i][j + 1] + bias[col + 1];
            v.z = acc[i][j + 2] + bias[col + 2];
            v.w = acc[i][j + 3] + bias[col + 3];
            if (doRelu) {
                v.x = fmaxf(v.x, 0.f); v.y = fmaxf(v.y, 0.f);
                v.z = fmaxf(v.z, 0.f); v.w = fmaxf(v.w, 0.f);
            }
            *reinterpret_cast<float4*>(&C[row * 256 + col]) = v;
        }
    }
}

// -------------------- fc3 (256->10) + log_softmax --------------------------
__global__ void k_final(const float* __restrict__ xf, const float* __restrict__ w,
                        const float* __restrict__ bias, float* __restrict__ out)
{
    int b = blockIdx.x;
    __shared__ float xs[HID];
    __shared__ float logits[10];
    xs[threadIdx.x] = xf[b * HID + threadIdx.x];
    __syncthreads();
    if (threadIdx.x < 10) {
        float s = bias[threadIdx.x];
        const float* wr = w + threadIdx.x * HID;
        for (int c = 0; c < HID; c++) s += wr[c] * xs[c];
        logits[threadIdx.x] = s;
    }
    __syncthreads();
    if (threadIdx.x == 0) {
        float mx = -1e30f;
        for (int n = 0; n < 10; n++) mx = fmaxf(mx, logits[n]);
        float se = 0.f;
        for (int n = 0; n < 10; n++) se += expf(logits[n] - mx);
        float lse = logf(se) + mx;
        for (int n = 0; n < 10; n++) out[b * 10 + n] = logits[n] - lse;
    }
}

// ---------------------------------------------------------------------------
static void* sym(const void* devSymbol)
{
    void* p = nullptr;
    cudaGetSymbolAddress(&p, devSymbol);
    return p;
}

static int conv_smem(int Cin, int Hin, int ohPer)
{
    int pitch = Hin + 2;
    int rowsAlloc = 2 * ohPer + 1;
    int swOff = (Cin * rowsAlloc * pitch + 3) & ~3;
    return (swOff + FS * Cin * 12 + FS) * 4;
}

extern "C" void kernel_launch(void* const* d_in, const int* in_sizes, int n_in,
                              void* d_out, int out_size)
{
    const float* img  = (const float*)d_in[0];
    const float* qst  = (const float*)d_in[1];
    const float* cw[4] = { (const float*)d_in[2],  (const float*)d_in[6],
                           (const float*)d_in[10], (const float*)d_in[14] };
    const float* cb[4] = { (const float*)d_in[3],  (const float*)d_in[7],
                           (const float*)d_in[11], (const float*)d_in[15] };
    const float* bg[4] = { (const float*)d_in[4],  (const float*)d_in[8],
                           (const float*)d_in[12], (const float*)d_in[16] };
    const float* bb[4] = { (const float*)d_in[5],  (const float*)d_in[9],
                           (const float*)d_in[13], (const float*)d_in[17] };
    const float* g1w = (const float*)d_in[18]; const float* g1b = (const float*)d_in[19];
    const float* g2w = (const float*)d_in[20]; const float* g2b = (const float*)d_in[21];
    const float* g3w = (const float*)d_in[22]; const float* g3b = (const float*)d_in[23];
    const float* g4w = (const float*)d_in[24]; const float* g4b = (const float*)d_in[25];
    const float* f1w = (const float*)d_in[26]; const float* f1b = (const float*)d_in[27];
    const float* fc2w = (const float*)d_in[28]; const float* fc2b = (const float*)d_in[29];
    const float* fc3w = (const float*)d_in[30]; const float* fc3b = (const float*)d_in[31];

    float* c1 = (float*)sym(g_c1); float* c2 = (float*)sym(g_c2);
    float* c3 = (float*)sym(g_c3); float* c4 = (float*)sym(g_c4);
    float* st = (float*)sym(g_stats4);
    float* P = (float*)sym(g_P); float* Q = (float*)sym(g_Q); float* R = (float*)sym(g_R);
    __half* wh = (__half*)sym(g_wh);
    float* xg = (float*)sym(g_xg); float* xf1 = (float*)sym(g_xf1); float* xf2 = (float*)sym(g_xf2);
    float* out = (float*)d_out;

    int sm1 = conv_smem(3, 80, 10);     // L1 split 4
    int sm2 = conv_smem(FS, 40, 10);    // L2 split 2
    int sm3 = conv_smem(FS, 20, 5);     // L3 split 2
    int sm4 = conv_smem(FS, 10, 5);     // L4 full
    int smMax = sm1;
    if (sm2 > smMax) smMax = sm2;
    if (sm3 > smMax) smMax = sm3;
    if (sm4 > smMax) smMax = sm4;

    cudaFuncSetAttribute(k_gchain, cudaFuncAttributeMaxDynamicSharedMemorySize, FSM_TOT);
    cudaFuncSetAttribute(k_convsm, cudaFuncAttributeMaxDynamicSharedMemorySize, smMax);

    k_zerostats<<<1, 192>>>(st);
    k_zeroxg<<<BATCH, HID>>>(xg);

    // ---- conv stack (row-split CTAs) ----
    k_convsm<<<dim3(BATCH, 4), 512, sm1>>>(img, cw[0], cb[0], c1,
                                           nullptr, st + 0 * 48, nullptr, nullptr,
                                           0.f, 3, 80, 40, 10);
    k_convsm<<<dim3(BATCH, 2), 512, sm2>>>(c1, cw[1], cb[1], c2,
                                           st + 0 * 48, st + 1 * 48, bg[0], bb[0],
                                           (float)(BATCH * 1600), FS, 40, 20, 10);
    k_convsm<<<dim3(BATCH, 2), 512, sm3>>>(c2, cw[2], cb[2], c3,
                                           st + 1 * 48, st + 2 * 48, bg[1], bb[1],
                                           (float)(BATCH * 400), FS, 20, 10, 5);
    k_convsm<<<dim3(BATCH, 1), 512, sm4>>>(c3, cw[3], cb[3], c4,
                                           st + 2 * 48, st + 3 * 48, bg[2], bb[2],
                                           (float)(BATCH * 100), FS, 10, 5, 5);

    // fp16 weight copies
    k_w2h<<<(HID * HID + 255) / 256, 256>>>(g2w, wh);
    k_w2h<<<(HID * HID + 255) / 256, 256>>>(g3w, wh + HID * HID);
    k_w2h<<<(HID * HID + 255) / 256, 256>>>(g4w, wh + 2 * HID * HID);

    // g1 projections (BN4 applied inside objproj)
    k_objproj<<<BATCH, HID>>>(c4, st + 3 * 48, bg[3], bb[3], g1w, P, Q);
    k_qproj<<<BATCH, HID>>>(qst, g1w, g1b, R);

    // fused g2->g3->g4->pairsum (512 threads / 16 warps, R14 version)
    k_gchain<<<NPAIR / 128, 512, FSM_TOT>>>(wh, g2b, g3b, g4b, P, Q, R, xg);

    // f layers (fp32)
    dim3 gsmall(BATCH / 128, 2);
    k_gemm256<<<gsmall, 256>>>(xg, f1w, f1b, xf1, BATCH, 1);
    k_gemm256<<<gsmall, 256>>>(xf1, fc2w, fc2b, xf2, BATCH, 1);

    // fc3 + log_softmax
    k_final<<<BATCH, HID>>>(xf2, fc3w, fc3b, out);
}